// round 13
// baseline (speedup 1.0000x reference)
#include <cuda_runtime.h>
#include <cstdint>
#include <cstddef>

// MNIST_RNN: 2-layer LSTM (H=10), T=28, D=28, B=32768, + 10-way linear head.
// R11 = R10 resubmission (previous round was an infra failure, no data).
// R10 = R9 (2 elems per thread-pair, gates split across pair, f32x2 FMA,
// anti-LICM volatile LDS) +
//  (1) MUFU.TANH activations: tanh.approx.f32 directly; sigmoid via
//      0.5 + 0.5*tanh(x/2). MUFU per step halves, serial chains shrink.
//  (2) biases kept in registers (loaded once pre-loop) and folded into the
//      first accumulation row of each layer as the FFMA2 addend.

#define TT 28
#define DD 28
#define HH 10

typedef unsigned long long u64;
typedef unsigned int u32;

__device__ __forceinline__ u32 smem_u32(const void *p) {
    u32 a;
    asm("{ .reg .u64 t; cvta.to.shared.u64 t, %1; cvt.u32.u64 %0, t; }"
        : "=r"(a) : "l"(p));
    return a;
}
__device__ __forceinline__ u64 pack2(float lo, float hi) {
    u64 r;
    asm("mov.b64 %0, {%1, %2};" : "=l"(r) : "f"(lo), "f"(hi));
    return r;
}
__device__ __forceinline__ void unpack2(u64 v, float &lo, float &hi) {
    asm("mov.b64 {%0, %1}, %2;" : "=f"(lo), "=f"(hi) : "l"(v));
}
__device__ __forceinline__ u64 ffma2(u64 a, u64 b, u64 c) {
    u64 d;
    asm("fma.rn.f32x2 %0, %1, %2, %3;" : "=l"(d) : "l"(a), "l"(b), "l"(c));
    return d;
}
// Non-hoistable shared loads (volatile = opaque to LICM/CSE; see R3).
__device__ __forceinline__ void lds_v2u64(u64 &w0, u64 &w1, u32 addr) {
    asm volatile("ld.shared.v2.u64 {%0, %1}, [%2];"
                 : "=l"(w0), "=l"(w1) : "r"(addr));
}
__device__ __forceinline__ float shflx1_f(float v) {
    return __shfl_xor_sync(0xffffffffu, v, 1);
}
__device__ __forceinline__ u64 shflx1_u64(u64 v) {
    u32 lo, hi;
    asm("mov.b64 {%0, %1}, %2;" : "=r"(lo), "=r"(hi) : "l"(v));
    lo = __shfl_xor_sync(0xffffffffu, lo, 1);
    hi = __shfl_xor_sync(0xffffffffu, hi, 1);
    u64 r;
    asm("mov.b64 %0, {%1, %2};" : "=l"(r) : "r"(lo), "r"(hi));
    return r;
}

// MUFU.TANH-based activations: 1 MUFU each (vs 2-MUFU exp/rcp chains).
__device__ __forceinline__ float tanh_ap(float x) {
    float y;
    asm("tanh.approx.f32 %0, %1;" : "=f"(y) : "f"(x));
    return y;
}
__device__ __forceinline__ float sigf(float x) {
    return __fmaf_rn(0.5f, tanh_ap(0.5f * x), 0.5f);
}
__device__ __forceinline__ float tanhf_(float x) { return tanh_ap(x); }

// smem u64 blob offsets (u64 units). Per-role regions; row = 10 u64 = 80 B.
//  w0x [2][28][10] @0   w0h [2][10][10] @560   w1x @760   w1h @960
//  b0  [2][10]     @1160  b1 [2][10]    @1180
#define U_W0X 0
#define U_W0H 560
#define U_W1X 760
#define U_W1H 960
#define U_B0  1160
#define U_B1  1180
#define U_TOT 1200

// Accumulate one input row into this role's 10 local gate pairs (both elems).
#define ACCROW2S(Wt, row, xa, xb)                                       \
    {                                                                   \
        u64 _va = pack2((xa), (xa));                                    \
        u64 _vb = pack2((xb), (xb));                                    \
        _Pragma("unroll")                                               \
        for (int qq = 0; qq < 5; qq++) {                                \
            u64 _w0, _w1;                                               \
            lds_v2u64(_w0, _w1, (Wt) + ((row) * 5 + qq) * 16);          \
            aA[2 * qq]     = ffma2(_va, _w0, aA[2 * qq]);               \
            aA[2 * qq + 1] = ffma2(_va, _w1, aA[2 * qq + 1]);           \
            aB[2 * qq]     = ffma2(_vb, _w0, aB[2 * qq]);               \
            aB[2 * qq + 1] = ffma2(_vb, _w1, aB[2 * qq + 1]);           \
        }                                                               \
    }

// First row of a layer: accumulator init = bias regs as FFMA2 addend.
#define ACCROW2S_INIT(Wt, row, xa, xb, bb)                              \
    {                                                                   \
        u64 _va = pack2((xa), (xa));                                    \
        u64 _vb = pack2((xb), (xb));                                    \
        _Pragma("unroll")                                               \
        for (int qq = 0; qq < 5; qq++) {                                \
            u64 _w0, _w1;                                               \
            lds_v2u64(_w0, _w1, (Wt) + ((row) * 5 + qq) * 16);          \
            aA[2 * qq]     = ffma2(_va, _w0, bb[2 * qq]);               \
            aA[2 * qq + 1] = ffma2(_va, _w1, bb[2 * qq + 1]);           \
            aB[2 * qq]     = ffma2(_vb, _w0, bb[2 * qq]);               \
            aB[2 * qq + 1] = ffma2(_vb, _w1, bb[2 * qq + 1]);           \
        }                                                               \
    }

#define ACCROW2S4(Wt, base, va4, vb4)                                   \
    ACCROW2S(Wt, (base) + 0, (va4).x, (vb4).x)                          \
    ACCROW2S(Wt, (base) + 1, (va4).y, (vb4).y)                          \
    ACCROW2S(Wt, (base) + 2, (va4).z, (vb4).z)                          \
    ACCROW2S(Wt, (base) + 3, (va4).w, (vb4).w)

#define ACCH2S(Wt, hA, hB)                                              \
    ACCROW2S(Wt, 0, hA[0], hB[0]) ACCROW2S(Wt, 1, hA[1], hB[1])         \
    ACCROW2S(Wt, 2, hA[2], hB[2]) ACCROW2S(Wt, 3, hA[3], hB[3])         \
    ACCROW2S(Wt, 4, hA[4], hB[4]) ACCROW2S(Wt, 5, hA[5], hB[5])         \
    ACCROW2S(Wt, 6, hA[6], hB[6]) ACCROW2S(Wt, 7, hA[7], hB[7])         \
    ACCROW2S(Wt, 8, hA[8], hB[8]) ACCROW2S(Wt, 9, hA[9], hB[9])

// Exchange accs with partner lane, update MY element's cell state (cv),
// write role-resolved hA/hB arrays for the next accumulation.
// role0: my elem = A, own accs = i,f; partner supplies g,o of A.
// role1: my elem = B, own accs = g,o; partner supplies i,f of B.
#define EXCH_UPDATE(hA, hB, cv)                                         \
    {                                                                   \
        u64 rcv[10];                                                    \
        _Pragma("unroll")                                               \
        for (int k = 0; k < 10; k++) {                                  \
            u64 snd = role ? aA[k] : aB[k];                             \
            rcv[k] = shflx1_u64(snd);                                   \
        }                                                               \
        _Pragma("unroll")                                               \
        for (int jj = 0; jj < 5; jj++) {                                \
            u64 Pi = role ? rcv[jj]     : aA[jj];                       \
            u64 Pf = role ? rcv[5 + jj] : aA[5 + jj];                   \
            u64 Pg = role ? aB[jj]      : rcv[jj];                      \
            u64 Po = role ? aB[5 + jj]  : rcv[5 + jj];                  \
            float i0, i1, f0, f1, g0, g1, o0, o1;                       \
            unpack2(Pi, i0, i1); unpack2(Pf, f0, f1);                   \
            unpack2(Pg, g0, g1); unpack2(Po, o0, o1);                   \
            float cn0 = sigf(f0) * cv[2 * jj]     + sigf(i0) * tanhf_(g0); \
            float cn1 = sigf(f1) * cv[2 * jj + 1] + sigf(i1) * tanhf_(g1); \
            cv[2 * jj] = cn0; cv[2 * jj + 1] = cn1;                     \
            float hm0 = sigf(o0) * tanhf_(cn0);                         \
            float hm1 = sigf(o1) * tanhf_(cn1);                         \
            float ho0 = shflx1_f(hm0);                                  \
            float ho1 = shflx1_f(hm1);                                  \
            hA[2 * jj]     = role ? ho0 : hm0;                          \
            hB[2 * jj]     = role ? hm0 : ho0;                          \
            hA[2 * jj + 1] = role ? ho1 : hm1;                          \
            hB[2 * jj + 1] = role ? hm1 : ho1;                          \
        }                                                               \
    }

__global__ __launch_bounds__(32)
void mnist_rnn_kernel(const float *__restrict__ x,
                      const float *__restrict__ wih0, const float *__restrict__ whh0,
                      const float *__restrict__ bih0, const float *__restrict__ bhh0,
                      const float *__restrict__ wih1, const float *__restrict__ whh1,
                      const float *__restrict__ bih1, const float *__restrict__ bhh1,
                      const float *__restrict__ wcls, const float *__restrict__ bcls,
                      float *__restrict__ out, int B) {
    __shared__ u64 blob[U_TOT];
    __shared__ float swc[100], sbc[10];

    const int tid = threadIdx.x;
    {
        float *f = (float *)blob;
        for (int i = tid; i < 1120; i += 32) {              // w0x
            int r = i / 560, rem = i % 560;
            int d = rem / 20, gg = rem % 20;
            f[i] = wih0[(20 * r + gg) * DD + d];
        }
        for (int i = tid; i < 400; i += 32) {               // w0h/w1x/w1h
            int r = i / 200, rem = i % 200;
            int j = rem / 20, gg = rem % 20;
            f[1120 + i] = whh0[(20 * r + gg) * HH + j];
            f[1520 + i] = wih1[(20 * r + gg) * HH + j];
            f[1920 + i] = whh1[(20 * r + gg) * HH + j];
        }
        for (int i = tid; i < 40; i += 32) {                // biases
            int r = i / 20, gg = i % 20;
            f[2320 + i] = bih0[20 * r + gg] + bhh0[20 * r + gg];
            f[2360 + i] = bih1[20 * r + gg] + bhh1[20 * r + gg];
        }
        for (int i = tid; i < 100; i += 32) swc[i] = wcls[i];
        for (int i = tid; i < 10; i += 32) sbc[i] = bcls[i];
    }
    __syncthreads();

    const u32 sbase = smem_u32(blob);
    const int role = tid & 1;
    const u32 w0x_t = sbase + U_W0X * 8 + role * (28 * 80);
    const u32 w0h_t = sbase + U_W0H * 8 + role * (10 * 80);
    const u32 w1x_t = sbase + U_W1X * 8 + role * (10 * 80);
    const u32 w1h_t = sbase + U_W1H * 8 + role * (10 * 80);
    const u32 sb0_t = sbase + U_B0 * 8 + role * 80;
    const u32 sb1_t = sbase + U_B1 * 8 + role * 80;

    // biases into registers once (outside the t-loop; volatile executes once)
    u64 bb0[10], bb1[10];
#pragma unroll
    for (int qq = 0; qq < 5; qq++) {
        lds_v2u64(bb0[2 * qq], bb0[2 * qq + 1], sb0_t + qq * 16);
        lds_v2u64(bb1[2 * qq], bb1[2 * qq + 1], sb1_t + qq * 16);
    }

    const int Bh = B >> 1;
    const int pairIdx = blockIdx.x * 16 + (tid >> 1);
    if (pairIdx >= Bh) return;
    const int bA = pairIdx, bB = pairIdx + Bh;

    const float *xbA = x + (size_t)bA * (TT * DD);
    const float *xbB = x + (size_t)bB * (TT * DD);

    float h0A[HH], h0B[HH], h1A[HH], h1B[HH];   // role-resolved hidden states
    float c0m[HH], c1m[HH];                      // MY element's cell states
#pragma unroll
    for (int j = 0; j < HH; j++) {
        h0A[j] = 0.f; h0B[j] = 0.f; h1A[j] = 0.f; h1B[j] = 0.f;
        c0m[j] = 0.f; c1m[j] = 0.f;
    }

#pragma unroll 1
    for (int t = 0; t < TT; t++) {
        const float4 *xrA = reinterpret_cast<const float4 *>(xbA + t * DD);
        const float4 *xrB = reinterpret_cast<const float4 *>(xbB + t * DD);

        u64 aA[10], aB[10];

        // ---- layer 0: x projection (bias folded into row 0) ----
        float4 vac = xrA[0], vbc = xrB[0];
        float4 van = xrA[1], vbn = xrB[1];
        ACCROW2S_INIT(w0x_t, 0, vac.x, vbc.x, bb0)
        ACCROW2S(w0x_t, 1, vac.y, vbc.y)
        ACCROW2S(w0x_t, 2, vac.z, vbc.z)
        ACCROW2S(w0x_t, 3, vac.w, vbc.w)
        vac = van; vbc = vbn; van = xrA[2]; vbn = xrB[2];
        ACCROW2S4(w0x_t, 4, vac, vbc)
        vac = van; vbc = vbn; van = xrA[3]; vbn = xrB[3];
        ACCROW2S4(w0x_t, 8, vac, vbc)
        vac = van; vbc = vbn; van = xrA[4]; vbn = xrB[4];
        ACCROW2S4(w0x_t, 12, vac, vbc)
        vac = van; vbc = vbn; van = xrA[5]; vbn = xrB[5];
        ACCROW2S4(w0x_t, 16, vac, vbc)
        vac = van; vbc = vbn; van = xrA[6]; vbn = xrB[6];
        ACCROW2S4(w0x_t, 20, vac, vbc)
        vac = van; vbc = vbn;
        ACCROW2S4(w0x_t, 24, vac, vbc)

        // recurrent part of layer 0, then exchange + pointwise update
        ACCH2S(w0h_t, h0A, h0B)
        EXCH_UPDATE(h0A, h0B, c0m)

        // ---- layer 1 (bias folded into first w1x row) ----
        ACCROW2S_INIT(w1x_t, 0, h0A[0], h0B[0], bb1)
        ACCROW2S(w1x_t, 1, h0A[1], h0B[1])
        ACCROW2S(w1x_t, 2, h0A[2], h0B[2])
        ACCROW2S(w1x_t, 3, h0A[3], h0B[3])
        ACCROW2S(w1x_t, 4, h0A[4], h0B[4])
        ACCROW2S(w1x_t, 5, h0A[5], h0B[5])
        ACCROW2S(w1x_t, 6, h0A[6], h0B[6])
        ACCROW2S(w1x_t, 7, h0A[7], h0B[7])
        ACCROW2S(w1x_t, 8, h0A[8], h0B[8])
        ACCROW2S(w1x_t, 9, h0A[9], h0B[9])
        ACCH2S(w1h_t, h1A, h1B)
        EXCH_UPDATE(h1A, h1B, c1m)
    }

    // classifier head: each thread writes its own element
    const int bm = role ? bB : bA;
#pragma unroll
    for (int k = 0; k < 10; k++) {
        float s = sbc[k];
#pragma unroll
        for (int j = 0; j < HH; j++) {
            float hm = role ? h1B[j] : h1A[j];
            s += hm * swc[k * HH + j];
        }
        out[(size_t)bm * 10 + k] = s;
    }
}

extern "C" void kernel_launch(void *const *d_in, const int *in_sizes, int n_in,
                              void *d_out, int out_size) {
    const float *x    = (const float *)d_in[0];
    const float *wih0 = (const float *)d_in[1];
    const float *whh0 = (const float *)d_in[2];
    const float *bih0 = (const float *)d_in[3];
    const float *bhh0 = (const float *)d_in[4];
    const float *wih1 = (const float *)d_in[5];
    const float *whh1 = (const float *)d_in[6];
    const float *bih1 = (const float *)d_in[7];
    const float *bhh1 = (const float *)d_in[8];
    const float *wcls = (const float *)d_in[9];
    const float *bcls = (const float *)d_in[10];
    float *out = (float *)d_out;

    const int B = in_sizes[0] / (TT * DD);
    const int Bh = B >> 1;
    const int grid = (Bh + 15) / 16;
    mnist_rnn_kernel<<<grid, 32>>>(x, wih0, whh0, bih0, bhh0,
                                   wih1, whh1, bih1, bhh1,
                                   wcls, bcls, out, B);
}